// round 12
// baseline (speedup 1.0000x reference)
#include <cuda_runtime.h>
#include <cstdint>

// out[r] = sum_{e: row[e]==r} val[e] * embs[col[e]]
// E = 3.2M, N = 100K, D = 128, fp32.
//
// Two-pass CSR: counting-sort edges by row (hist -> scan -> permute into
// static scratch), then warp-per-row SpMM with register accumulation and a
// single 512B STG per row. Eliminates the 1.64GB RED scatter stream that
// bound L1TEX (83.9%) in the edge-parallel version; gather (1.64GB random
// 512B from L2-resident embs) is the remaining floor.

#define MAX_E 3200000
#define MAX_N 100000
#define SCAN_T 1024

__device__ int   g_cnt[MAX_N];       // per-row degree (histogram)
__device__ int   g_row_ptr[MAX_N + 1];
__device__ int   g_off[MAX_N];       // running scatter offsets
__device__ int   g_col[MAX_E];       // row-sorted cols
__device__ float g_val[MAX_E];       // row-sorted vals

__global__ void zero_kernel(int n)
{
    int i = blockIdx.x * blockDim.x + threadIdx.x;
    if (i < n) g_cnt[i] = 0;
}

__global__ void hist_kernel(const int* __restrict__ edge_row, int e_cnt)
{
    int e = blockIdx.x * blockDim.x + threadIdx.x;
    if (e < e_cnt) atomicAdd(&g_cnt[edge_row[e]], 1);
}

// Single-CTA exclusive scan over n counters (n ~ 100K). Each thread sums a
// contiguous chunk, thread 0 serially scans the 1024 partials, then each
// thread writes prefix values over its chunk.
__global__ void __launch_bounds__(SCAN_T)
scan_kernel(int n)
{
    __shared__ int sums[SCAN_T];
    const int t = threadIdx.x;
    const int chunk = (n + SCAN_T - 1) / SCAN_T;
    const int lo = t * chunk;
    const int hi = min(lo + chunk, n);

    int s = 0;
    for (int i = lo; i < hi; i++) s += g_cnt[i];
    sums[t] = s;
    __syncthreads();

    if (t == 0) {
        int run = 0;
        for (int i = 0; i < SCAN_T; i++) {
            int x = sums[i];
            sums[i] = run;
            run += x;
        }
        g_row_ptr[n] = run;   // total edge count
    }
    __syncthreads();

    int run = sums[t];
    for (int i = lo; i < hi; i++) {
        g_row_ptr[i] = run;
        g_off[i]     = run;
        run += g_cnt[i];
    }
}

__global__ void scatter_kernel(const int* __restrict__ edge_row,
                               const int* __restrict__ edge_col,
                               const float* __restrict__ edge_val,
                               int e_cnt)
{
    int e = blockIdx.x * blockDim.x + threadIdx.x;
    if (e >= e_cnt) return;
    const int r = edge_row[e];
    const int pos = atomicAdd(&g_off[r], 1);
    g_col[pos] = edge_col[e];
    g_val[pos] = edge_val[e];
}

// Warp per row: coalesced (col,val) list reads, chunk-of-8 batched gathers
// (MLP ~8 against ~240-cyc L2 latency), FMA into 2 register accumulators,
// one 512B STG per row. Rows average deg 32 (Poisson).
__global__ void __launch_bounds__(256)
spmm_kernel(const float4* __restrict__ embs4,   // [N, 32] float4
            float4* __restrict__ out4,          // [N, 32] float4
            int n_nodes)
{
    const int lane = threadIdx.x & 31;
    const int r = (blockIdx.x * blockDim.x + threadIdx.x) >> 5;
    if (r >= n_nodes) return;

    const int start = g_row_ptr[r];
    const int end   = g_row_ptr[r + 1];

    float4 acc0 = make_float4(0.f, 0.f, 0.f, 0.f);
    float4 acc1 = make_float4(0.f, 0.f, 0.f, 0.f);

    for (int j0 = start; j0 < end; j0 += 32) {
        // Coalesced load of up to 32 (col,val) pairs for this row.
        int   c = 0;
        float v = 0.0f;
        const int e = j0 + lane;
        if (e < end) {
            c = g_col[e];
            v = g_val[e];
        }
        const int cnt = min(32, end - j0);

        int j = 0;
        for (; j + 8 <= cnt; j += 8) {
            int   cj[8];
            float vj[8];
            #pragma unroll
            for (int k = 0; k < 8; k++) {
                cj[k] = __shfl_sync(0xffffffffu, c, j + k);
                vj[k] = __shfl_sync(0xffffffffu, v, j + k);
            }
            // 8 independent 512B gathers -> high MLP on L2-resident embs.
            float4 m[8];
            #pragma unroll
            for (int k = 0; k < 8; k++)
                m[k] = __ldg(&embs4[(size_t)cj[k] * 32 + lane]);
            #pragma unroll
            for (int k = 0; k < 8; k++) {
                float4& a = (k & 1) ? acc1 : acc0;
                a.x = fmaf(vj[k], m[k].x, a.x);
                a.y = fmaf(vj[k], m[k].y, a.y);
                a.z = fmaf(vj[k], m[k].z, a.z);
                a.w = fmaf(vj[k], m[k].w, a.w);
            }
        }
        for (; j < cnt; j++) {
            const int   cj = __shfl_sync(0xffffffffu, c, j);
            const float vj = __shfl_sync(0xffffffffu, v, j);
            float4 m = __ldg(&embs4[(size_t)cj * 32 + lane]);
            acc0.x = fmaf(vj, m.x, acc0.x);
            acc0.y = fmaf(vj, m.y, acc0.y);
            acc0.z = fmaf(vj, m.z, acc0.z);
            acc0.w = fmaf(vj, m.w, acc0.w);
        }
    }

    acc0.x += acc1.x; acc0.y += acc1.y;
    acc0.z += acc1.z; acc0.w += acc1.w;
    out4[(size_t)r * 32 + lane] = acc0;   // covers empty rows with zeros
}

extern "C" void kernel_launch(void* const* d_in, const int* in_sizes, int n_in,
                              void* d_out, int out_size)
{
    const int*    edge_row = (const int*)   d_in[0];
    const int*    edge_col = (const int*)   d_in[1];
    const float*  edge_val = (const float*) d_in[2];
    const float4* embs4    = (const float4*)d_in[3];

    const int n_edges = in_sizes[0];
    const int n_nodes = out_size / 128;   // D = 128 floats per row
    float4* out4 = (float4*)d_out;

    const int T = 256;
    const int eb = (n_edges + T - 1) / T;
    const int nb = (n_nodes + T - 1) / T;

    zero_kernel<<<nb, T>>>(n_nodes);
    hist_kernel<<<eb, T>>>(edge_row, n_edges);
    scan_kernel<<<1, SCAN_T>>>(n_nodes);
    scatter_kernel<<<eb, T>>>(edge_row, edge_col, edge_val, n_edges);

    const int warps = n_nodes;                 // warp per row
    const int sb = (warps * 32 + T - 1) / T;
    spmm_kernel<<<sb, T>>>(embs4, out4, n_nodes);
}